// round 13
// baseline (speedup 1.0000x reference)
#include <cuda_runtime.h>
#include <stdint.h>

#define BATCH 16
#define H 1024
#define W 1024
#define HW (H*W)            // 1<<20
#define NPIX (BATCH*HW)
#define BGLAB 0xFFFFu

// ---------------- scratch (static device globals; no allocs) ----------------
__device__ unsigned short d_label16[NPIX];
__device__ int d_labels[NPIX];
__device__ int d_counts[NPIX];
__device__ unsigned long long d_winner[BATCH];

__device__ __forceinline__ int recon(int base, int rowbase, int colbase, int v) {
    return base + ((rowbase + (v >> 5)) << 10) + colbase + (v & 31);
}

// ---------------- shared-memory union-find (min-index roots) ----------------
// Read-only find: trees stay shallow (unions enter at run leaders), so the
// halving atomicMin traffic costs more than it saves.
__device__ __forceinline__ int findRootS(int* L, int x) {
    int p = L[x];
    while (p != x) { x = p; p = L[x]; }
    return p;
}
__device__ __forceinline__ void uniteS(int* L, int a, int b) {
    a = findRootS(L, a);
    b = findRootS(L, b);
    while (a != b) {
        if (a < b) { int t = a; a = b; b = t; }
        int old = atomicMin(&L[a], b);
        if (old == a) a = b;
        else a = old;
    }
}

// ---------------- global union-find with path halving -----------------------
__device__ __forceinline__ int findRootH(int x) {
    int p = d_labels[x];
    while (p != x) {
        int gp = d_labels[p];
        if (gp != p) atomicMin(&d_labels[x], gp);
        x = p; p = gp;
    }
    return x;
}
__device__ __forceinline__ void uniteG(int a, int b) {
    a = findRootH(a);
    b = findRootH(b);
    while (a != b) {
        if (a < b) { int t = a; a = b; b = t; }
        int old = atomicMin(&d_labels[a], b);
        if (old == a) a = b;
        else a = old;
    }
}

// leader of column c in a 32-bit row mask (c must be a set bit)
__device__ __forceinline__ int runLeader(unsigned mask, int c) {
    const unsigned runstarts = mask & ~(mask << 1);
    return 31 - __clz(runstarts & ((2u << c) - 1u));
}

// ---------------- kernel 1: fg + run-based tile-local CC (256 thr) ----------
// Unions now enter at the LEADER on both sides (b-side leader computed from
// the up-row ballot mask) -- no pixel->leader hop anywhere in the union phase.
__global__ __launch_bounds__(256, 8) void k_init_local(const float* __restrict__ x) {
    __shared__ int sl[1024];
    __shared__ unsigned smask[32];

    const int tid = threadIdx.x;
    const int row = tid >> 3;           // 0..31
    const int col4 = (tid & 7) << 2;    // 0,4,...,28
    const int b = blockIdx.z;
    const int grow = (blockIdx.y << 5) + row;
    const int gcol = (blockIdx.x << 5) + col4;
    const int p = grow * W + gcol;
    const int g = b * HW + p;

    const float* xb = x + (size_t)b * 2 * HW;
    const float4 a0 = *(const float4*)(xb + p);
    const float4 a1 = *(const float4*)(xb + HW + p);

    unsigned nib = (a1.x > a0.x ? 1u : 0u) | (a1.y > a0.y ? 2u : 0u)
                 | (a1.z > a0.z ? 4u : 0u) | (a1.w > a0.w ? 8u : 0u);

    // OR-butterfly within 8-lane row groups -> full 32-bit row mask
    unsigned m = nib << (col4 & 31);
    m |= __shfl_xor_sync(0xFFFFFFFFu, m, 1);
    m |= __shfl_xor_sync(0xFFFFFFFFu, m, 2);
    m |= __shfl_xor_sync(0xFFFFFFFFu, m, 4);
    if ((tid & 7) == 0) smask[row] = m;

    // run leaders for the 4 pixels
    const int r32 = row << 5;
    int n0 = r32 + col4, n1 = n0 + 1, n2 = n0 + 2, n3 = n0 + 3;
    if (nib & 1u) n0 = r32 + runLeader(m, col4);
    if (nib & 2u) n1 = r32 + runLeader(m, col4 + 1);
    if (nib & 4u) n2 = r32 + runLeader(m, col4 + 2);
    if (nib & 8u) n3 = r32 + runLeader(m, col4 + 3);
    *(int4*)&sl[r32 + col4] = make_int4(n0, n1, n2, n3);
    __syncthreads();

    const int nodes[4] = {n0, n1, n2, n3};
    if (row > 0 && nib) {
        const unsigned up = smask[row - 1];
        const int u32 = (row - 1) << 5;
        #pragma unroll
        for (int j = 0; j < 4; ++j) {
            if (!((nib >> j) & 1u)) continue;
            const int c = col4 + j;
            const bool Wf  = (c > 0)  && ((m >> (c - 1)) & 1u);
            const bool Ef  = (c < 31) && ((m >> (c + 1)) & 1u);
            const bool Nf  = (up >> c) & 1u;
            const bool NWf = (c > 0)  && ((up >> (c - 1)) & 1u);
            const bool NEf = (c < 31) && ((up >> (c + 1)) & 1u);
            if (Nf) {
                if (!(Wf && NWf)) uniteS(sl, nodes[j], u32 + runLeader(up, c));
            } else {
                if (NWf && !Wf) uniteS(sl, nodes[j], u32 + runLeader(up, c - 1));
                if (NEf && !Ef) uniteS(sl, nodes[j], u32 + runLeader(up, c + 1));
            }
        }
    }
    __syncthreads();

    // leader-only resolution + compression; root leaders do the sparse init
    #pragma unroll
    for (int j = 0; j < 4; ++j) {
        if ((nib >> j) & 1u) {
            const int t = r32 + col4 + j;
            if (nodes[j] == t) {                     // run leader
                const int r = findRootS(sl, t);
                sl[t] = r;                           // compress (true root)
                if (r == t) { d_labels[g + j] = g + j; d_counts[g + j] = 0; }
            }
        }
    }
    __syncthreads();

    // per-pixel final label: one shared read of the leader entry
    unsigned short v[4];
    #pragma unroll
    for (int j = 0; j < 4; ++j)
        v[j] = ((nib >> j) & 1u) ? (unsigned short)sl[nodes[j]]
                                 : (unsigned short)BGLAB;
    *(ushort4*)&d_label16[g] = make_ushort4(v[0], v[1], v[2], v[3]);
}

// ---------------- kernel 2: run-filtered cross-tile border merges -----------
__global__ void k_border() {
    const int perB = 2 * 31 * 1024;
    const int idx = blockIdx.x * blockDim.x + threadIdx.x;
    if (idx < BATCH) d_winner[idx] = 0ULL;     // reset winners (pre-k3)
    if (idx >= BATCH * perB) return;
    const int b = idx / perB;
    int j = idx - b * perB;
    const int base = b * HW;

    if (j < 31 * 1024) {
        const int r = 32 * (1 + (j >> 10));
        const int c = j & 1023;
        const int lane = c & 31;
        const int p = base + r * W + c;

        const int v  = d_label16[p];
        const int vn = d_label16[p - W];
        int nwv = __shfl_up_sync(0xFFFFFFFFu, vn, 1);
        int nev = __shfl_down_sync(0xFFFFFFFFu, vn, 1);
        if (lane == 0)  nwv = (c > 0)    ? (int)d_label16[p - W - 1] : (int)BGLAB;
        if (lane == 31) nev = (c < 1023) ? (int)d_label16[p - W + 1] : (int)BGLAB;
        const unsigned rowm = __ballot_sync(0xFFFFFFFFu, v != (int)BGLAB);
        const unsigned upm  = __ballot_sync(0xFFFFFFFFu, vn != (int)BGLAB);
        if (v == (int)BGLAB) return;

        const bool Wf  = lane > 0  && ((rowm >> (lane - 1)) & 1u);
        const bool Ef  = lane < 31 && ((rowm >> (lane + 1)) & 1u);
        const bool Nf  = (upm >> lane) & 1u;
        const bool NWf = nwv != (int)BGLAB;
        const bool NEf = nev != (int)BGLAB;

        const int lp = recon(base, r, c & ~31, v);
        if (Nf) {
            if (!(Wf && NWf)) uniteG(lp, recon(base, r - 32, c & ~31, vn));
        } else {
            if (NWf && !Wf) uniteG(lp, recon(base, r - 32, (c - 1) & ~31, nwv));
            if (NEf && !Ef) uniteG(lp, recon(base, r - 32, (c + 1) & ~31, nev));
        }
    } else {
        j -= 31 * 1024;
        const int c = 32 * (1 + (j >> 10));
        const int r = j & 1023;
        const int lane = r & 31;
        const int p = base + r * W + c;

        const int v  = d_label16[p];
        const int wv = d_label16[p - 1];
        int nwv = __shfl_up_sync(0xFFFFFFFFu, wv, 1);
        int swv = __shfl_down_sync(0xFFFFFFFFu, wv, 1);
        if (lane == 0)  nwv = (r > 0)    ? (int)d_label16[p - W - 1] : (int)BGLAB;
        if (lane == 31) swv = (r < 1023) ? (int)d_label16[p + W - 1] : (int)BGLAB;
        const unsigned colm = __ballot_sync(0xFFFFFFFFu, v != (int)BGLAB);
        __syncwarp();
        if (v == (int)BGLAB) return;

        const bool Nf  = lane > 0  && ((colm >> (lane - 1)) & 1u);
        const bool Sf  = lane < 31 && ((colm >> (lane + 1)) & 1u);
        const bool Wf  = wv  != (int)BGLAB;
        const bool NWf = nwv != (int)BGLAB;
        const bool SWf = swv != (int)BGLAB;

        const int lp = recon(base, r & ~31, c, v);
        if (Wf) {
            if (!(Nf && NWf)) uniteG(lp, recon(base, r & ~31, c - 32, wv));
        } else {
            if (NWf && !Nf) uniteG(lp, recon(base, (r - 1) & ~31, c - 32, nwv));
            if (SWf && !Sf) uniteG(lp, recon(base, (r + 1) & ~31, c - 32, swv));
        }
    }
}

// ---------------- kernel 3: quad-aggregated count + compress + winner -------
// Per-thread ushort4: equal adjacent labels (runs) are merged BEFORE touching
// shared counters (~2 atomics/thread instead of 4). Then tile roots chase to
// final roots (full compression), block-aggregate (final_root,cnt) in a hash,
// one global atomicAdd per distinct final root per block. Winner-key argument:
// adds partition the true total, every partial <= total, chronologically-last
// add returns the exact total => max key = (max count, min root).
__global__ __launch_bounds__(256, 8) void k_count() {
    __shared__ int hcnt[1024];
    __shared__ int agk[256];
    __shared__ int agv[256];
    __shared__ unsigned long long blockmax;

    const int tid = threadIdx.x;
    const int row = tid >> 3;
    const int col4 = (tid & 7) << 2;
    const int b = blockIdx.z;
    const int base = b * HW;
    const int g = base + (((blockIdx.y << 5) + row) << 10) + (blockIdx.x << 5) + col4;

    *(int4*)&hcnt[tid << 2] = make_int4(0, 0, 0, 0);
    agk[tid] = -1;
    agv[tid] = 0;
    if (tid == 0) blockmax = 0ULL;
    __syncthreads();

    const ushort4 lv = *(const ushort4*)&d_label16[g];
    {
        // aggregate equal adjacent labels in the quad
        const unsigned short q[4] = {lv.x, lv.y, lv.z, lv.w};
        int i = 0;
        while (i < 4) {
            const unsigned short lab = q[i];
            int cnt = 1;
            while (i + cnt < 4 && q[i + cnt] == lab) ++cnt;
            if (lab != (unsigned short)BGLAB) atomicAdd(&hcnt[lab], cnt);
            i += cnt;
        }
    }
    __syncthreads();

    const int4 cnts = *(const int4*)&hcnt[tid << 2];
    const int cv[4] = {cnts.x, cnts.y, cnts.z, cnts.w};
    unsigned long long localmax = 0ULL;
    #pragma unroll
    for (int j = 0; j < 4; ++j) {
        const int cnt = cv[j];
        if (cnt > 0) {
            const int node = recon(base, blockIdx.y << 5, blockIdx.x << 5, (tid << 2) + j);
            int r = node, pc = d_labels[node];
            while (pc != r) { r = pc; pc = d_labels[r]; }
            int xx = node;
            while (xx != r) { int nxt = d_labels[xx]; d_labels[xx] = r; xx = nxt; }

            unsigned h = ((unsigned)r * 2654435761u) >> 24;
            bool done = false;
            for (int probe = 0; probe < 256; ++probe) {
                const int slot = (h + probe) & 255;
                const int k = atomicCAS(&agk[slot], -1, r);
                if (k == -1 || k == r) { atomicAdd(&agv[slot], cnt); done = true; break; }
            }
            if (!done) {
                const int total = atomicAdd(&d_counts[r], cnt) + cnt;
                const unsigned long long key =
                    ((unsigned long long)(unsigned)total << 32)
                    | (unsigned long long)(0xFFFFFFFFu - (unsigned)r);
                if (key > localmax) localmax = key;
            }
        }
    }
    __syncthreads();

    const int fk = agk[tid];
    if (fk >= 0) {
        const int cnt = agv[tid];
        const int total = atomicAdd(&d_counts[fk], cnt) + cnt;
        const unsigned long long key =
            ((unsigned long long)(unsigned)total << 32)
            | (unsigned long long)(0xFFFFFFFFu - (unsigned)fk);
        if (key > localmax) localmax = key;
    }
    if (localmax) atomicMax(&blockmax, localmax);
    __syncthreads();

    if (tid == 0 && blockmax != 0ULL) {
        unsigned long long cur = *(volatile unsigned long long*)&d_winner[b];
        if (blockmax > cur) atomicMax(&d_winner[b], blockmax);
    }
}

// ---------------- kernel 4: masked output -----------------------------------
__global__ void k_write(const float* __restrict__ x, float* __restrict__ out) {
    const int i = blockIdx.x * blockDim.x + threadIdx.x;   // over NPIX/4
    const int p4 = i << 2;
    const int b = p4 >> 20;                                // HW = 2^20
    const int p = p4 & (HW - 1);

    const unsigned long long wk = d_winner[b];
    const int wroot = (int)(0xFFFFFFFFu - (unsigned)(wk & 0xFFFFFFFFu)); // no fg -> -1

    const ushort4 lv = ((const ushort4*)d_label16)[i];
    const int base = b * HW;
    const int rowbase = (p >> 10) & ~31;
    const int colbase = p & 0x3E0;

    const bool m0 = (lv.x != BGLAB) && (d_labels[recon(base, rowbase, colbase, lv.x)] == wroot);
    const bool m1 = (lv.y != BGLAB) && (d_labels[recon(base, rowbase, colbase, lv.y)] == wroot);
    const bool m2 = (lv.z != BGLAB) && (d_labels[recon(base, rowbase, colbase, lv.z)] == wroot);
    const bool m3 = (lv.w != BGLAB) && (d_labels[recon(base, rowbase, colbase, lv.w)] == wroot);

    const float* xb = x + (size_t)b * 2 * HW;
    const float4 v0 = *(const float4*)(xb + p);
    const float4 v1 = *(const float4*)(xb + HW + p);

    float4 o0, o1;
    o0.x = m0 ? v0.x : 0.0f;
    o0.y = m1 ? v0.y : 0.0f;
    o0.z = m2 ? v0.z : 0.0f;
    o0.w = m3 ? v0.w : 0.0f;
    o1.x = m0 ? v1.x : 0.0f;
    o1.y = m1 ? v1.y : 0.0f;
    o1.z = m2 ? v1.z : 0.0f;
    o1.w = m3 ? v1.w : 0.0f;

    float* ob = out + (size_t)b * 2 * HW;
    *(float4*)(ob + p) = o0;
    *(float4*)(ob + HW + p) = o1;
}

// ---------------- launcher --------------------------------------------------
extern "C" void kernel_launch(void* const* d_in, const int* in_sizes, int n_in,
                              void* d_out, int out_size) {
    const float* x = (const float*)d_in[0];
    float* out = (float*)d_out;

    dim3 grd(W / 32, H / 32, BATCH);

    k_init_local<<<grd, 256>>>(x);

    const int nb = BATCH * 2 * 31 * 1024;
    k_border<<<(nb + 255) / 256, 256>>>();

    k_count<<<grd, 256>>>();

    k_write<<<(NPIX / 4) / 256, 256>>>(x, out);
}

// round 14
// speedup vs baseline: 1.0605x; 1.0605x over previous
#include <cuda_runtime.h>
#include <stdint.h>

#define BATCH 16
#define H 1024
#define W 1024
#define HW (H*W)            // 1<<20
#define NPIX (BATCH*HW)
#define BGLAB 0xFFFFu

// ---------------- scratch (static device globals; no allocs) ----------------
// d_label16[g]: tile-local root id (0..1023) for fg pixels, 0xFFFF for bg.
// d_labels:     union-find parent store; ONLY tile-root entries are touched.
// d_counts:     seeded by k1 at tile roots with the root's LOCAL pixel count;
//               k3 accumulates final totals at final roots.
__device__ unsigned short d_label16[NPIX];
__device__ int d_labels[NPIX];
__device__ int d_counts[NPIX];
__device__ unsigned long long d_winner[BATCH];

__device__ __forceinline__ int recon(int base, int rowbase, int colbase, int v) {
    return base + ((rowbase + (v >> 5)) << 10) + colbase + (v & 31);
}

// ---------------- shared-memory union-find (min-index roots) ----------------
__device__ __forceinline__ int findRootSH(int* L, int x) {   // with path halving
    int p = L[x];
    while (p != x) {
        int gp = L[p];
        if (gp != p) atomicMin(&L[x], gp);
        x = p; p = gp;
    }
    return x;
}
__device__ __forceinline__ int findRootS(int* L, int x) {    // read-only chase
    int p = L[x];
    while (p != x) { x = p; p = L[x]; }
    return p;
}
__device__ __forceinline__ void uniteS(int* L, int a, int b) {
    a = findRootSH(L, a);
    b = findRootSH(L, b);
    while (a != b) {
        if (a < b) { int t = a; a = b; b = t; }
        int old = atomicMin(&L[a], b);
        if (old == a) a = b;
        else a = old;
    }
}

// ---------------- global union-find with path halving -----------------------
__device__ __forceinline__ int findRootH(int x) {
    int p = d_labels[x];
    while (p != x) {
        int gp = d_labels[p];
        if (gp != p) atomicMin(&d_labels[x], gp);
        x = p; p = gp;
    }
    return x;
}
__device__ __forceinline__ void uniteG(int a, int b) {
    a = findRootH(a);
    b = findRootH(b);
    while (a != b) {
        if (a < b) { int t = a; a = b; b = t; }
        int old = atomicMin(&d_labels[a], b);
        if (old == a) a = b;
        else a = old;
    }
}

// ---------------- kernel 1: fg + run-based tile-local CC + count seeding ----
__global__ __launch_bounds__(256, 8) void k_init_local(const float* __restrict__ x) {
    __shared__ int sl[1024];
    __shared__ int scnt[1024];
    __shared__ unsigned smask[32];

    const int tid = threadIdx.x;
    const int row = tid >> 3;           // 0..31
    const int col4 = (tid & 7) << 2;    // 0,4,...,28
    const int b = blockIdx.z;
    const int grow = (blockIdx.y << 5) + row;
    const int gcol = (blockIdx.x << 5) + col4;
    const int p = grow * W + gcol;
    const int g = b * HW + p;

    const float* xb = x + (size_t)b * 2 * HW;
    const float4 a0 = *(const float4*)(xb + p);
    const float4 a1 = *(const float4*)(xb + HW + p);

    unsigned nib = (a1.x > a0.x ? 1u : 0u) | (a1.y > a0.y ? 2u : 0u)
                 | (a1.z > a0.z ? 4u : 0u) | (a1.w > a0.w ? 8u : 0u);

    // OR-butterfly within 8-lane row groups -> full 32-bit row mask
    unsigned m = nib << (col4 & 31);
    m |= __shfl_xor_sync(0xFFFFFFFFu, m, 1);
    m |= __shfl_xor_sync(0xFFFFFFFFu, m, 2);
    m |= __shfl_xor_sync(0xFFFFFFFFu, m, 4);
    if ((tid & 7) == 0) smask[row] = m;

    // run leaders for the 4 pixels
    const unsigned runstarts = m & ~(m << 1);
    const int r32 = row << 5;
    int n0 = r32 + col4, n1 = n0 + 1, n2 = n0 + 2, n3 = n0 + 3;
    if (nib & 1u) n0 = r32 + (31 - __clz(runstarts & ((2u << (col4    )) - 1u)));
    if (nib & 2u) n1 = r32 + (31 - __clz(runstarts & ((2u << (col4 + 1)) - 1u)));
    if (nib & 4u) n2 = r32 + (31 - __clz(runstarts & ((2u << (col4 + 2)) - 1u)));
    if (nib & 8u) n3 = r32 + (31 - __clz(runstarts & ((2u << (col4 + 3)) - 1u)));
    *(int4*)&sl[r32 + col4] = make_int4(n0, n1, n2, n3);
    *(int4*)&scnt[tid << 2] = make_int4(0, 0, 0, 0);
    __syncthreads();

    const int nodes[4] = {n0, n1, n2, n3};
    if (row > 0 && nib) {
        const unsigned up = smask[row - 1];
        #pragma unroll
        for (int j = 0; j < 4; ++j) {
            if (!((nib >> j) & 1u)) continue;
            const int c = col4 + j;
            const int t = r32 + c;
            const bool Wf  = (c > 0)  && ((m >> (c - 1)) & 1u);
            const bool Ef  = (c < 31) && ((m >> (c + 1)) & 1u);
            const bool Nf  = (up >> c) & 1u;
            const bool NWf = (c > 0)  && ((up >> (c - 1)) & 1u);
            const bool NEf = (c < 31) && ((up >> (c + 1)) & 1u);
            if (Nf) {
                if (!(Wf && NWf)) uniteS(sl, nodes[j], t - 32);
            } else {
                if (NWf && !Wf) uniteS(sl, nodes[j], t - 33);
                if (NEf && !Ef) uniteS(sl, nodes[j], t - 31);
            }
        }
    }
    __syncthreads();

    // leader-only resolution + compression + run-length accumulation
    #pragma unroll
    for (int j = 0; j < 4; ++j) {
        if ((nib >> j) & 1u) {
            const int c = col4 + j;
            const int t = r32 + c;
            if (nodes[j] == t) {                     // run leader
                const int r = findRootS(sl, t);
                sl[t] = r;                           // compress (true root)
                const unsigned rest = ~(m >> c);
                const int runlen = rest ? (__ffs(rest) - 1) : (32 - c);
                atomicAdd(&scnt[r], runlen);
            }
        }
    }
    __syncthreads();

    // export roots: seed d_labels (self) and d_counts (local count)
    {
        const int base = b * HW;
        const int rowbase = blockIdx.y << 5;
        const int colbase = blockIdx.x << 5;
        const int4 sc = *(const int4*)&scnt[tid << 2];
        const int scv[4] = {sc.x, sc.y, sc.z, sc.w};
        #pragma unroll
        for (int j = 0; j < 4; ++j) {
            if (scv[j] > 0) {
                const int node = recon(base, rowbase, colbase, (tid << 2) + j);
                d_labels[node] = node;
                d_counts[node] = scv[j];
            }
        }
    }

    // per-pixel final label: one shared read of the leader entry
    unsigned short v[4];
    #pragma unroll
    for (int j = 0; j < 4; ++j)
        v[j] = ((nib >> j) & 1u) ? (unsigned short)sl[nodes[j]]
                                 : (unsigned short)BGLAB;
    *(ushort4*)&d_label16[g] = make_ushort4(v[0], v[1], v[2], v[3]);
}

// ---------------- kernel 2: run-filtered cross-tile border merges -----------
__global__ void k_border() {
    const int perB = 2 * 31 * 1024;
    const int idx = blockIdx.x * blockDim.x + threadIdx.x;
    if (idx < BATCH) d_winner[idx] = 0ULL;     // reset winners (pre-k3)
    if (idx >= BATCH * perB) return;
    const int b = idx / perB;
    int j = idx - b * perB;
    const int base = b * HW;

    if (j < 31 * 1024) {
        const int r = 32 * (1 + (j >> 10));
        const int c = j & 1023;
        const int lane = c & 31;
        const int p = base + r * W + c;

        const int v  = d_label16[p];
        const int vn = d_label16[p - W];
        int nwv = __shfl_up_sync(0xFFFFFFFFu, vn, 1);
        int nev = __shfl_down_sync(0xFFFFFFFFu, vn, 1);
        if (lane == 0)  nwv = (c > 0)    ? (int)d_label16[p - W - 1] : (int)BGLAB;
        if (lane == 31) nev = (c < 1023) ? (int)d_label16[p - W + 1] : (int)BGLAB;
        const unsigned rowm = __ballot_sync(0xFFFFFFFFu, v != (int)BGLAB);
        const unsigned upm  = __ballot_sync(0xFFFFFFFFu, vn != (int)BGLAB);
        if (v == (int)BGLAB) return;

        const bool Wf  = lane > 0  && ((rowm >> (lane - 1)) & 1u);
        const bool Ef  = lane < 31 && ((rowm >> (lane + 1)) & 1u);
        const bool Nf  = (upm >> lane) & 1u;
        const bool NWf = nwv != (int)BGLAB;
        const bool NEf = nev != (int)BGLAB;

        const int lp = recon(base, r, c & ~31, v);
        if (Nf) {
            if (!(Wf && NWf)) uniteG(lp, recon(base, r - 32, c & ~31, vn));
        } else {
            if (NWf && !Wf) uniteG(lp, recon(base, r - 32, (c - 1) & ~31, nwv));
            if (NEf && !Ef) uniteG(lp, recon(base, r - 32, (c + 1) & ~31, nev));
        }
    } else {
        j -= 31 * 1024;
        const int c = 32 * (1 + (j >> 10));
        const int r = j & 1023;
        const int lane = r & 31;
        const int p = base + r * W + c;

        const int v  = d_label16[p];
        const int wv = d_label16[p - 1];
        int nwv = __shfl_up_sync(0xFFFFFFFFu, wv, 1);
        int swv = __shfl_down_sync(0xFFFFFFFFu, wv, 1);
        if (lane == 0)  nwv = (r > 0)    ? (int)d_label16[p - W - 1] : (int)BGLAB;
        if (lane == 31) swv = (r < 1023) ? (int)d_label16[p + W - 1] : (int)BGLAB;
        const unsigned colm = __ballot_sync(0xFFFFFFFFu, v != (int)BGLAB);
        __syncwarp();
        if (v == (int)BGLAB) return;

        const bool Nf  = lane > 0  && ((colm >> (lane - 1)) & 1u);
        const bool Sf  = lane < 31 && ((colm >> (lane + 1)) & 1u);
        const bool Wf  = wv  != (int)BGLAB;
        const bool NWf = nwv != (int)BGLAB;
        const bool SWf = swv != (int)BGLAB;

        const int lp = recon(base, r & ~31, c, v);
        if (Wf) {
            if (!(Nf && NWf)) uniteG(lp, recon(base, r & ~31, c - 32, wv));
        } else {
            if (NWf && !Nf) uniteG(lp, recon(base, (r - 1) & ~31, c - 32, nwv));
            if (SWf && !Sf) uniteG(lp, recon(base, (r + 1) & ~31, c - 32, swv));
        }
    }
}

// ---------------- kernel 3: seeded totals: compress + aggregate + winner ----
// A pixel is a tile root iff label16 == its own slot id (register compare; no
// histogram, no shared atomics). Roots chase to the FINAL root with full path
// compression. cnt = own seed for non-final roots (entries that are never add
// targets -> race-free read), 0 for final roots (seed pre-loaded by k1).
// Block-aggregated adds (one global atomicAdd per distinct final root per
// block). Winner key: every add partial <= total; the chronologically-last
// add (or the 0-add for single-tile components) carries the exact total, so
// max key = (max count, min root) -- jnp.argmax tie-break preserved.
__global__ __launch_bounds__(256, 8) void k_count() {
    __shared__ int agk[256];
    __shared__ int agv[256];
    __shared__ unsigned long long blockmax;

    const int tid = threadIdx.x;
    const int row = tid >> 3;
    const int col4 = (tid & 7) << 2;
    const int b = blockIdx.z;
    const int base = b * HW;
    const int g = base + (((blockIdx.y << 5) + row) << 10) + (blockIdx.x << 5) + col4;
    const int slot0 = (row << 5) + col4;

    agk[tid] = -1;
    agv[tid] = 0;
    if (tid == 0) blockmax = 0ULL;
    __syncthreads();

    const ushort4 lv = *(const ushort4*)&d_label16[g];
    const unsigned short q[4] = {lv.x, lv.y, lv.z, lv.w};
    unsigned long long localmax = 0ULL;
    #pragma unroll
    for (int j = 0; j < 4; ++j) {
        if ((int)q[j] == slot0 + j) {                // tile root
            const int node = g + j;
            int r = node, pc = d_labels[node];
            while (pc != r) { r = pc; pc = d_labels[r]; }
            int xx = node;
            while (xx != r) { int nxt = d_labels[xx]; d_labels[xx] = r; xx = nxt; }

            const int cnt = (node == r) ? 0 : d_counts[node];

            unsigned h = ((unsigned)r * 2654435761u) >> 24;
            bool done = false;
            for (int probe = 0; probe < 256; ++probe) {
                const int slot = (h + probe) & 255;
                const int k = atomicCAS(&agk[slot], -1, r);
                if (k == -1 || k == r) { atomicAdd(&agv[slot], cnt); done = true; break; }
            }
            if (!done) {
                const int total = atomicAdd(&d_counts[r], cnt) + cnt;
                const unsigned long long key =
                    ((unsigned long long)(unsigned)total << 32)
                    | (unsigned long long)(0xFFFFFFFFu - (unsigned)r);
                if (key > localmax) localmax = key;
            }
        }
    }
    __syncthreads();

    // flush: one global atomicAdd per distinct final root in this block
    const int fk = agk[tid];
    if (fk >= 0) {
        const int cnt = agv[tid];
        const int total = atomicAdd(&d_counts[fk], cnt) + cnt;
        const unsigned long long key =
            ((unsigned long long)(unsigned)total << 32)
            | (unsigned long long)(0xFFFFFFFFu - (unsigned)fk);
        if (key > localmax) localmax = key;
    }
    if (localmax) atomicMax(&blockmax, localmax);
    __syncthreads();

    if (tid == 0 && blockmax != 0ULL) {
        unsigned long long cur = *(volatile unsigned long long*)&d_winner[b];
        if (blockmax > cur) atomicMax(&d_winner[b], blockmax);
    }
}

// ---------------- kernel 4: masked output -----------------------------------
__global__ void k_write(const float* __restrict__ x, float* __restrict__ out) {
    const int i = blockIdx.x * blockDim.x + threadIdx.x;   // over NPIX/4
    const int p4 = i << 2;
    const int b = p4 >> 20;                                // HW = 2^20
    const int p = p4 & (HW - 1);

    const unsigned long long wk = d_winner[b];
    const int wroot = (int)(0xFFFFFFFFu - (unsigned)(wk & 0xFFFFFFFFu)); // no fg -> -1

    const ushort4 lv = ((const ushort4*)d_label16)[i];
    const int base = b * HW;
    const int rowbase = (p >> 10) & ~31;
    const int colbase = p & 0x3E0;

    const bool m0 = (lv.x != BGLAB) && (d_labels[recon(base, rowbase, colbase, lv.x)] == wroot);
    const bool m1 = (lv.y != BGLAB) && (d_labels[recon(base, rowbase, colbase, lv.y)] == wroot);
    const bool m2 = (lv.z != BGLAB) && (d_labels[recon(base, rowbase, colbase, lv.z)] == wroot);
    const bool m3 = (lv.w != BGLAB) && (d_labels[recon(base, rowbase, colbase, lv.w)] == wroot);

    const float* xb = x + (size_t)b * 2 * HW;
    const float4 v0 = *(const float4*)(xb + p);
    const float4 v1 = *(const float4*)(xb + HW + p);

    float4 o0, o1;
    o0.x = m0 ? v0.x : 0.0f;
    o0.y = m1 ? v0.y : 0.0f;
    o0.z = m2 ? v0.z : 0.0f;
    o0.w = m3 ? v0.w : 0.0f;
    o1.x = m0 ? v1.x : 0.0f;
    o1.y = m1 ? v1.y : 0.0f;
    o1.z = m2 ? v1.z : 0.0f;
    o1.w = m3 ? v1.w : 0.0f;

    float* ob = out + (size_t)b * 2 * HW;
    *(float4*)(ob + p) = o0;
    *(float4*)(ob + HW + p) = o1;
}

// ---------------- launcher --------------------------------------------------
extern "C" void kernel_launch(void* const* d_in, const int* in_sizes, int n_in,
                              void* d_out, int out_size) {
    const float* x = (const float*)d_in[0];
    float* out = (float*)d_out;

    dim3 grd(W / 32, H / 32, BATCH);

    k_init_local<<<grd, 256>>>(x);

    const int nb = BATCH * 2 * 31 * 1024;
    k_border<<<(nb + 255) / 256, 256>>>();

    k_count<<<grd, 256>>>();

    k_write<<<(NPIX / 4) / 256, 256>>>(x, out);
}

// round 15
// speedup vs baseline: 1.0786x; 1.0171x over previous
#include <cuda_runtime.h>
#include <stdint.h>

#define BATCH 16
#define H 1024
#define W 1024
#define HW (H*W)            // 1<<20
#define NPIX (BATCH*HW)
#define BGLAB 0xFFFFu

// ---------------- scratch (static device globals; no allocs) ----------------
__device__ unsigned short d_label16[NPIX];
__device__ int d_labels[NPIX];
__device__ int d_counts[NPIX];
__device__ unsigned long long d_winner[BATCH];

__device__ __forceinline__ int recon(int base, int rowbase, int colbase, int v) {
    return base + ((rowbase + (v >> 5)) << 10) + colbase + (v & 31);
}

// ---------------- shared-memory union-find (min-index roots) ----------------
__device__ __forceinline__ int findRootSH(int* L, int x) {   // with path halving
    int p = L[x];
    while (p != x) {
        int gp = L[p];
        if (gp != p) atomicMin(&L[x], gp);
        x = p; p = gp;
    }
    return x;
}
__device__ __forceinline__ int findRootS(int* L, int x) {    // read-only chase
    int p = L[x];
    while (p != x) { x = p; p = L[x]; }
    return p;
}
__device__ __forceinline__ void uniteS(int* L, int a, int b) {
    a = findRootSH(L, a);
    b = findRootSH(L, b);
    while (a != b) {
        if (a < b) { int t = a; a = b; b = t; }
        int old = atomicMin(&L[a], b);
        if (old == a) a = b;
        else a = old;
    }
}

// ---------------- global union-find with path halving -----------------------
__device__ __forceinline__ int findRootH(int x) {
    int p = d_labels[x];
    while (p != x) {
        int gp = d_labels[p];
        if (gp != p) atomicMin(&d_labels[x], gp);
        x = p; p = gp;
    }
    return x;
}
__device__ __forceinline__ void uniteG(int a, int b) {
    a = findRootH(a);
    b = findRootH(b);
    while (a != b) {
        if (a < b) { int t = a; a = b; b = t; }
        int old = atomicMin(&d_labels[a], b);
        if (old == a) a = b;
        else a = old;
    }
}

// ---------------- kernel 1: fg + run-based tile-local CC (256 thr) ----------
__global__ __launch_bounds__(256, 8) void k_init_local(const float* __restrict__ x) {
    __shared__ int sl[1024];
    __shared__ unsigned smask[32];

    const int tid = threadIdx.x;
    const int row = tid >> 3;           // 0..31
    const int col4 = (tid & 7) << 2;    // 0,4,...,28
    const int b = blockIdx.z;
    const int grow = (blockIdx.y << 5) + row;
    const int gcol = (blockIdx.x << 5) + col4;
    const int p = grow * W + gcol;
    const int g = b * HW + p;

    const float* xb = x + (size_t)b * 2 * HW;
    const float4 a0 = *(const float4*)(xb + p);
    const float4 a1 = *(const float4*)(xb + HW + p);

    unsigned nib = (a1.x > a0.x ? 1u : 0u) | (a1.y > a0.y ? 2u : 0u)
                 | (a1.z > a0.z ? 4u : 0u) | (a1.w > a0.w ? 8u : 0u);

    // OR-butterfly within 8-lane row groups -> full 32-bit row mask
    unsigned m = nib << (col4 & 31);
    m |= __shfl_xor_sync(0xFFFFFFFFu, m, 1);
    m |= __shfl_xor_sync(0xFFFFFFFFu, m, 2);
    m |= __shfl_xor_sync(0xFFFFFFFFu, m, 4);
    if ((tid & 7) == 0) smask[row] = m;

    // run leaders for the 4 pixels
    const unsigned runstarts = m & ~(m << 1);
    const int r32 = row << 5;
    int n0 = r32 + col4, n1 = n0 + 1, n2 = n0 + 2, n3 = n0 + 3;
    if (nib & 1u) n0 = r32 + (31 - __clz(runstarts & ((2u << (col4    )) - 1u)));
    if (nib & 2u) n1 = r32 + (31 - __clz(runstarts & ((2u << (col4 + 1)) - 1u)));
    if (nib & 4u) n2 = r32 + (31 - __clz(runstarts & ((2u << (col4 + 2)) - 1u)));
    if (nib & 8u) n3 = r32 + (31 - __clz(runstarts & ((2u << (col4 + 3)) - 1u)));
    *(int4*)&sl[r32 + col4] = make_int4(n0, n1, n2, n3);
    __syncthreads();

    const int nodes[4] = {n0, n1, n2, n3};
    if (row > 0 && nib) {
        const unsigned up = smask[row - 1];
        #pragma unroll
        for (int j = 0; j < 4; ++j) {
            if (!((nib >> j) & 1u)) continue;
            const int c = col4 + j;
            const int t = r32 + c;
            const bool Wf  = (c > 0)  && ((m >> (c - 1)) & 1u);
            const bool Ef  = (c < 31) && ((m >> (c + 1)) & 1u);
            const bool Nf  = (up >> c) & 1u;
            const bool NWf = (c > 0)  && ((up >> (c - 1)) & 1u);
            const bool NEf = (c < 31) && ((up >> (c + 1)) & 1u);
            if (Nf) {
                if (!(Wf && NWf)) uniteS(sl, nodes[j], t - 32);
            } else {
                if (NWf && !Wf) uniteS(sl, nodes[j], t - 33);
                if (NEf && !Ef) uniteS(sl, nodes[j], t - 31);
            }
        }
    }
    __syncthreads();

    // leader-only resolution + compression; root leaders do the sparse init
    #pragma unroll
    for (int j = 0; j < 4; ++j) {
        if ((nib >> j) & 1u) {
            const int t = r32 + col4 + j;
            if (nodes[j] == t) {                     // run leader
                const int r = findRootS(sl, t);
                sl[t] = r;                           // compress (true root)
                if (r == t) { d_labels[g + j] = g + j; d_counts[g + j] = 0; }
            }
        }
    }
    __syncthreads();

    // per-pixel final label with quad-level leader dedup: repeated leaders in
    // the quad cost a register compare instead of an extra LDS (~35% fewer
    // scattered shared reads in this phase at p=0.5).
    unsigned short v[4];
    int lastNode = -1;
    unsigned short lastV = (unsigned short)BGLAB;
    #pragma unroll
    for (int j = 0; j < 4; ++j) {
        if ((nib >> j) & 1u) {
            if (nodes[j] != lastNode) {
                lastNode = nodes[j];
                lastV = (unsigned short)sl[lastNode];
            }
            v[j] = lastV;
        } else {
            v[j] = (unsigned short)BGLAB;
        }
    }
    *(ushort4*)&d_label16[g] = make_ushort4(v[0], v[1], v[2], v[3]);
}

// ---------------- kernel 2: run-filtered cross-tile border merges -----------
__global__ void k_border() {
    const int perB = 2 * 31 * 1024;
    const int idx = blockIdx.x * blockDim.x + threadIdx.x;
    if (idx < BATCH) d_winner[idx] = 0ULL;     // reset winners (pre-k3)
    if (idx >= BATCH * perB) return;
    const int b = idx / perB;
    int j = idx - b * perB;
    const int base = b * HW;

    if (j < 31 * 1024) {
        const int r = 32 * (1 + (j >> 10));
        const int c = j & 1023;
        const int lane = c & 31;
        const int p = base + r * W + c;

        const int v  = d_label16[p];
        const int vn = d_label16[p - W];
        int nwv = __shfl_up_sync(0xFFFFFFFFu, vn, 1);
        int nev = __shfl_down_sync(0xFFFFFFFFu, vn, 1);
        if (lane == 0)  nwv = (c > 0)    ? (int)d_label16[p - W - 1] : (int)BGLAB;
        if (lane == 31) nev = (c < 1023) ? (int)d_label16[p - W + 1] : (int)BGLAB;
        const unsigned rowm = __ballot_sync(0xFFFFFFFFu, v != (int)BGLAB);
        const unsigned upm  = __ballot_sync(0xFFFFFFFFu, vn != (int)BGLAB);
        if (v == (int)BGLAB) return;

        const bool Wf  = lane > 0  && ((rowm >> (lane - 1)) & 1u);
        const bool Ef  = lane < 31 && ((rowm >> (lane + 1)) & 1u);
        const bool Nf  = (upm >> lane) & 1u;
        const bool NWf = nwv != (int)BGLAB;
        const bool NEf = nev != (int)BGLAB;

        const int lp = recon(base, r, c & ~31, v);
        if (Nf) {
            if (!(Wf && NWf)) uniteG(lp, recon(base, r - 32, c & ~31, vn));
        } else {
            if (NWf && !Wf) uniteG(lp, recon(base, r - 32, (c - 1) & ~31, nwv));
            if (NEf && !Ef) uniteG(lp, recon(base, r - 32, (c + 1) & ~31, nev));
        }
    } else {
        j -= 31 * 1024;
        const int c = 32 * (1 + (j >> 10));
        const int r = j & 1023;
        const int lane = r & 31;
        const int p = base + r * W + c;

        const int v  = d_label16[p];
        const int wv = d_label16[p - 1];
        int nwv = __shfl_up_sync(0xFFFFFFFFu, wv, 1);
        int swv = __shfl_down_sync(0xFFFFFFFFu, wv, 1);
        if (lane == 0)  nwv = (r > 0)    ? (int)d_label16[p - W - 1] : (int)BGLAB;
        if (lane == 31) swv = (r < 1023) ? (int)d_label16[p + W - 1] : (int)BGLAB;
        const unsigned colm = __ballot_sync(0xFFFFFFFFu, v != (int)BGLAB);
        __syncwarp();
        if (v == (int)BGLAB) return;

        const bool Nf  = lane > 0  && ((colm >> (lane - 1)) & 1u);
        const bool Sf  = lane < 31 && ((colm >> (lane + 1)) & 1u);
        const bool Wf  = wv  != (int)BGLAB;
        const bool NWf = nwv != (int)BGLAB;
        const bool SWf = swv != (int)BGLAB;

        const int lp = recon(base, r & ~31, c, v);
        if (Wf) {
            if (!(Nf && NWf)) uniteG(lp, recon(base, r & ~31, c - 32, wv));
        } else {
            if (NWf && !Nf) uniteG(lp, recon(base, (r - 1) & ~31, c - 32, nwv));
            if (SWf && !Sf) uniteG(lp, recon(base, (r + 1) & ~31, c - 32, swv));
        }
    }
}

// ---------------- kernel 3: count + compress + block-aggregated totals ------
__global__ __launch_bounds__(256, 8) void k_count() {
    __shared__ int hcnt[1024];
    __shared__ int agk[256];
    __shared__ int agv[256];
    __shared__ unsigned long long blockmax;

    const int tid = threadIdx.x;
    const int row = tid >> 3;
    const int col4 = (tid & 7) << 2;
    const int b = blockIdx.z;
    const int base = b * HW;
    const int g = base + (((blockIdx.y << 5) + row) << 10) + (blockIdx.x << 5) + col4;

    *(int4*)&hcnt[tid << 2] = make_int4(0, 0, 0, 0);
    agk[tid] = -1;
    agv[tid] = 0;
    if (tid == 0) blockmax = 0ULL;
    __syncthreads();

    const ushort4 lv = *(const ushort4*)&d_label16[g];
    if (lv.x != BGLAB) atomicAdd(&hcnt[lv.x], 1);
    if (lv.y != BGLAB) atomicAdd(&hcnt[lv.y], 1);
    if (lv.z != BGLAB) atomicAdd(&hcnt[lv.z], 1);
    if (lv.w != BGLAB) atomicAdd(&hcnt[lv.w], 1);
    __syncthreads();

    const int4 cnts = *(const int4*)&hcnt[tid << 2];
    const int cv[4] = {cnts.x, cnts.y, cnts.z, cnts.w};
    unsigned long long localmax = 0ULL;
    #pragma unroll
    for (int j = 0; j < 4; ++j) {
        const int cnt = cv[j];
        if (cnt > 0) {
            const int node = recon(base, blockIdx.y << 5, blockIdx.x << 5, (tid << 2) + j);
            int r = node, pc = d_labels[node];
            while (pc != r) { r = pc; pc = d_labels[r]; }
            int xx = node;
            while (xx != r) { int nxt = d_labels[xx]; d_labels[xx] = r; xx = nxt; }

            unsigned h = ((unsigned)r * 2654435761u) >> 24;
            bool done = false;
            for (int probe = 0; probe < 256; ++probe) {
                const int slot = (h + probe) & 255;
                const int k = atomicCAS(&agk[slot], -1, r);
                if (k == -1 || k == r) { atomicAdd(&agv[slot], cnt); done = true; break; }
            }
            if (!done) {
                const int total = atomicAdd(&d_counts[r], cnt) + cnt;
                const unsigned long long key =
                    ((unsigned long long)(unsigned)total << 32)
                    | (unsigned long long)(0xFFFFFFFFu - (unsigned)r);
                if (key > localmax) localmax = key;
            }
        }
    }
    __syncthreads();

    const int fk = agk[tid];
    if (fk >= 0) {
        const int cnt = agv[tid];
        const int total = atomicAdd(&d_counts[fk], cnt) + cnt;
        const unsigned long long key =
            ((unsigned long long)(unsigned)total << 32)
            | (unsigned long long)(0xFFFFFFFFu - (unsigned)fk);
        if (key > localmax) localmax = key;
    }
    if (localmax) atomicMax(&blockmax, localmax);
    __syncthreads();

    if (tid == 0 && blockmax != 0ULL) {
        unsigned long long cur = *(volatile unsigned long long*)&d_winner[b];
        if (blockmax > cur) atomicMax(&d_winner[b], blockmax);
    }
}

// ---------------- kernel 4: masked output -----------------------------------
__global__ void k_write(const float* __restrict__ x, float* __restrict__ out) {
    const int i = blockIdx.x * blockDim.x + threadIdx.x;   // over NPIX/4
    const int p4 = i << 2;
    const int b = p4 >> 20;                                // HW = 2^20
    const int p = p4 & (HW - 1);

    const unsigned long long wk = d_winner[b];
    const int wroot = (int)(0xFFFFFFFFu - (unsigned)(wk & 0xFFFFFFFFu)); // no fg -> -1

    const ushort4 lv = ((const ushort4*)d_label16)[i];
    const int base = b * HW;
    const int rowbase = (p >> 10) & ~31;
    const int colbase = p & 0x3E0;

    const bool m0 = (lv.x != BGLAB) && (d_labels[recon(base, rowbase, colbase, lv.x)] == wroot);
    const bool m1 = (lv.y != BGLAB) && (d_labels[recon(base, rowbase, colbase, lv.y)] == wroot);
    const bool m2 = (lv.z != BGLAB) && (d_labels[recon(base, rowbase, colbase, lv.z)] == wroot);
    const bool m3 = (lv.w != BGLAB) && (d_labels[recon(base, rowbase, colbase, lv.w)] == wroot);

    const float* xb = x + (size_t)b * 2 * HW;
    const float4 v0 = *(const float4*)(xb + p);
    const float4 v1 = *(const float4*)(xb + HW + p);

    float4 o0, o1;
    o0.x = m0 ? v0.x : 0.0f;
    o0.y = m1 ? v0.y : 0.0f;
    o0.z = m2 ? v0.z : 0.0f;
    o0.w = m3 ? v0.w : 0.0f;
    o1.x = m0 ? v1.x : 0.0f;
    o1.y = m1 ? v1.y : 0.0f;
    o1.z = m2 ? v1.z : 0.0f;
    o1.w = m3 ? v1.w : 0.0f;

    float* ob = out + (size_t)b * 2 * HW;
    *(float4*)(ob + p) = o0;
    *(float4*)(ob + HW + p) = o1;
}

// ---------------- launcher --------------------------------------------------
extern "C" void kernel_launch(void* const* d_in, const int* in_sizes, int n_in,
                              void* d_out, int out_size) {
    const float* x = (const float*)d_in[0];
    float* out = (float*)d_out;

    dim3 grd(W / 32, H / 32, BATCH);

    k_init_local<<<grd, 256>>>(x);

    const int nb = BATCH * 2 * 31 * 1024;
    k_border<<<(nb + 255) / 256, 256>>>();

    k_count<<<grd, 256>>>();

    k_write<<<(NPIX / 4) / 256, 256>>>(x, out);
}

// round 16
// speedup vs baseline: 1.0793x; 1.0007x over previous
#include <cuda_runtime.h>
#include <stdint.h>

#define BATCH 16
#define H 1024
#define W 1024
#define HW (H*W)            // 1<<20
#define NPIX (BATCH*HW)
#define BGLAB 0xFFFFu

// ---------------- scratch (static device globals; no allocs) ----------------
__device__ unsigned short d_label16[NPIX];
__device__ int d_labels[NPIX];
__device__ int d_counts[NPIX];
__device__ unsigned long long d_winner[BATCH];

__device__ __forceinline__ int recon(int base, int rowbase, int colbase, int v) {
    return base + ((rowbase + (v >> 5)) << 10) + colbase + (v & 31);
}

// ---------------- shared-memory union-find (min-index roots) ----------------
__device__ __forceinline__ int findRootSH(int* L, int x) {   // with path halving
    int p = L[x];
    while (p != x) {
        int gp = L[p];
        if (gp != p) atomicMin(&L[x], gp);
        x = p; p = gp;
    }
    return x;
}
__device__ __forceinline__ int findRootS(int* L, int x) {    // read-only chase
    int p = L[x];
    while (p != x) { x = p; p = L[x]; }
    return p;
}
__device__ __forceinline__ void uniteS(int* L, int a, int b) {
    a = findRootSH(L, a);
    b = findRootSH(L, b);
    while (a != b) {
        if (a < b) { int t = a; a = b; b = t; }
        int old = atomicMin(&L[a], b);
        if (old == a) a = b;
        else a = old;
    }
}

// ---------------- global union-find with path halving -----------------------
__device__ __forceinline__ int findRootH(int x) {
    int p = d_labels[x];
    while (p != x) {
        int gp = d_labels[p];
        if (gp != p) atomicMin(&d_labels[x], gp);
        x = p; p = gp;
    }
    return x;
}
__device__ __forceinline__ void uniteG(int a, int b) {
    a = findRootH(a);
    b = findRootH(b);
    while (a != b) {
        if (a < b) { int t = a; a = b; b = t; }
        int old = atomicMin(&d_labels[a], b);
        if (old == a) a = b;
        else a = old;
    }
}

// ---------------- kernel 1: fg + run-based tile-local CC (256 thr) ----------
__global__ __launch_bounds__(256, 8) void k_init_local(const float* __restrict__ x) {
    __shared__ int sl[1024];
    __shared__ unsigned smask[32];

    const int tid = threadIdx.x;
    const int row = tid >> 3;           // 0..31
    const int col4 = (tid & 7) << 2;    // 0,4,...,28
    const int b = blockIdx.z;
    const int grow = (blockIdx.y << 5) + row;
    const int gcol = (blockIdx.x << 5) + col4;
    const int p = grow * W + gcol;
    const int g = b * HW + p;

    const float* xb = x + (size_t)b * 2 * HW;
    const float4 a0 = *(const float4*)(xb + p);
    const float4 a1 = *(const float4*)(xb + HW + p);

    unsigned nib = (a1.x > a0.x ? 1u : 0u) | (a1.y > a0.y ? 2u : 0u)
                 | (a1.z > a0.z ? 4u : 0u) | (a1.w > a0.w ? 8u : 0u);

    // OR-butterfly within 8-lane row groups -> full 32-bit row mask
    unsigned m = nib << (col4 & 31);
    m |= __shfl_xor_sync(0xFFFFFFFFu, m, 1);
    m |= __shfl_xor_sync(0xFFFFFFFFu, m, 2);
    m |= __shfl_xor_sync(0xFFFFFFFFu, m, 4);
    if ((tid & 7) == 0) smask[row] = m;

    // run leaders for the 4 pixels
    const unsigned runstarts = m & ~(m << 1);
    const int r32 = row << 5;
    int n0 = r32 + col4, n1 = n0 + 1, n2 = n0 + 2, n3 = n0 + 3;
    if (nib & 1u) n0 = r32 + (31 - __clz(runstarts & ((2u << (col4    )) - 1u)));
    if (nib & 2u) n1 = r32 + (31 - __clz(runstarts & ((2u << (col4 + 1)) - 1u)));
    if (nib & 4u) n2 = r32 + (31 - __clz(runstarts & ((2u << (col4 + 2)) - 1u)));
    if (nib & 8u) n3 = r32 + (31 - __clz(runstarts & ((2u << (col4 + 3)) - 1u)));
    *(int4*)&sl[r32 + col4] = make_int4(n0, n1, n2, n3);
    __syncthreads();

    const int nodes[4] = {n0, n1, n2, n3};
    if (row > 0 && nib) {
        const unsigned up = smask[row - 1];
        #pragma unroll
        for (int j = 0; j < 4; ++j) {
            if (!((nib >> j) & 1u)) continue;
            const int c = col4 + j;
            const int t = r32 + c;
            const bool Wf  = (c > 0)  && ((m >> (c - 1)) & 1u);
            const bool Ef  = (c < 31) && ((m >> (c + 1)) & 1u);
            const bool Nf  = (up >> c) & 1u;
            const bool NWf = (c > 0)  && ((up >> (c - 1)) & 1u);
            const bool NEf = (c < 31) && ((up >> (c + 1)) & 1u);
            if (Nf) {
                if (!(Wf && NWf)) uniteS(sl, nodes[j], t - 32);
            } else {
                if (NWf && !Wf) uniteS(sl, nodes[j], t - 33);
                if (NEf && !Ef) uniteS(sl, nodes[j], t - 31);
            }
        }
    }
    __syncthreads();

    // leader-only resolution + compression; root leaders do the sparse init
    #pragma unroll
    for (int j = 0; j < 4; ++j) {
        if ((nib >> j) & 1u) {
            const int t = r32 + col4 + j;
            if (nodes[j] == t) {                     // run leader
                const int r = findRootS(sl, t);
                sl[t] = r;                           // compress (true root)
                if (r == t) { d_labels[g + j] = g + j; d_counts[g + j] = 0; }
            }
        }
    }
    __syncthreads();

    // per-pixel final label: one shared read of the leader entry
    unsigned short v[4];
    #pragma unroll
    for (int j = 0; j < 4; ++j)
        v[j] = ((nib >> j) & 1u) ? (unsigned short)sl[nodes[j]]
                                 : (unsigned short)BGLAB;
    *(ushort4*)&d_label16[g] = make_ushort4(v[0], v[1], v[2], v[3]);
}

// ---------------- kernel 2: run-filtered cross-tile border merges -----------
__global__ void k_border() {
    const int perB = 2 * 31 * 1024;
    const int idx = blockIdx.x * blockDim.x + threadIdx.x;
    if (idx < BATCH) d_winner[idx] = 0ULL;     // reset winners (pre-k3)
    if (idx >= BATCH * perB) return;
    const int b = idx / perB;
    int j = idx - b * perB;
    const int base = b * HW;

    if (j < 31 * 1024) {
        const int r = 32 * (1 + (j >> 10));
        const int c = j & 1023;
        const int lane = c & 31;
        const int p = base + r * W + c;

        const int v  = d_label16[p];
        const int vn = d_label16[p - W];
        int nwv = __shfl_up_sync(0xFFFFFFFFu, vn, 1);
        int nev = __shfl_down_sync(0xFFFFFFFFu, vn, 1);
        if (lane == 0)  nwv = (c > 0)    ? (int)d_label16[p - W - 1] : (int)BGLAB;
        if (lane == 31) nev = (c < 1023) ? (int)d_label16[p - W + 1] : (int)BGLAB;
        const unsigned rowm = __ballot_sync(0xFFFFFFFFu, v != (int)BGLAB);
        const unsigned upm  = __ballot_sync(0xFFFFFFFFu, vn != (int)BGLAB);
        if (v == (int)BGLAB) return;

        const bool Wf  = lane > 0  && ((rowm >> (lane - 1)) & 1u);
        const bool Ef  = lane < 31 && ((rowm >> (lane + 1)) & 1u);
        const bool Nf  = (upm >> lane) & 1u;
        const bool NWf = nwv != (int)BGLAB;
        const bool NEf = nev != (int)BGLAB;

        const int lp = recon(base, r, c & ~31, v);
        if (Nf) {
            if (!(Wf && NWf)) uniteG(lp, recon(base, r - 32, c & ~31, vn));
        } else {
            if (NWf && !Wf) uniteG(lp, recon(base, r - 32, (c - 1) & ~31, nwv));
            if (NEf && !Ef) uniteG(lp, recon(base, r - 32, (c + 1) & ~31, nev));
        }
    } else {
        j -= 31 * 1024;
        const int c = 32 * (1 + (j >> 10));
        const int r = j & 1023;
        const int lane = r & 31;
        const int p = base + r * W + c;

        const int v  = d_label16[p];
        const int wv = d_label16[p - 1];
        int nwv = __shfl_up_sync(0xFFFFFFFFu, wv, 1);
        int swv = __shfl_down_sync(0xFFFFFFFFu, wv, 1);
        if (lane == 0)  nwv = (r > 0)    ? (int)d_label16[p - W - 1] : (int)BGLAB;
        if (lane == 31) swv = (r < 1023) ? (int)d_label16[p + W - 1] : (int)BGLAB;
        const unsigned colm = __ballot_sync(0xFFFFFFFFu, v != (int)BGLAB);
        __syncwarp();
        if (v == (int)BGLAB) return;

        const bool Nf  = lane > 0  && ((colm >> (lane - 1)) & 1u);
        const bool Sf  = lane < 31 && ((colm >> (lane + 1)) & 1u);
        const bool Wf  = wv  != (int)BGLAB;
        const bool NWf = nwv != (int)BGLAB;
        const bool SWf = swv != (int)BGLAB;

        const int lp = recon(base, r & ~31, c, v);
        if (Wf) {
            if (!(Nf && NWf)) uniteG(lp, recon(base, r & ~31, c - 32, wv));
        } else {
            if (NWf && !Nf) uniteG(lp, recon(base, (r - 1) & ~31, c - 32, nwv));
            if (SWf && !Sf) uniteG(lp, recon(base, (r + 1) & ~31, c - 32, swv));
        }
    }
}

// ---------------- kernel 3: match_any-reduced count + compress + winner -----
// Histogram phase: __match_any_sync groups lanes holding the SAME label per
// quad slot; only the group leader issues one shared atomicAdd with popc as
// the count (~4x fewer shared atomics; totals identical). The rest is R12:
// tile roots chase to final roots (full compression), block-aggregate
// (final_root,cnt) in a shared hash, one global atomicAdd per distinct final
// root per block. Winner key: adds partition the true total, every partial <=
// total, chronologically-last add returns the exact total => max key =
// (max count, min root) -- jnp.argmax tie-break preserved.
__global__ __launch_bounds__(256, 8) void k_count() {
    __shared__ int hcnt[1024];
    __shared__ int agk[256];
    __shared__ int agv[256];
    __shared__ unsigned long long blockmax;

    const int tid = threadIdx.x;
    const int row = tid >> 3;
    const int col4 = (tid & 7) << 2;
    const int b = blockIdx.z;
    const int base = b * HW;
    const int g = base + (((blockIdx.y << 5) + row) << 10) + (blockIdx.x << 5) + col4;

    *(int4*)&hcnt[tid << 2] = make_int4(0, 0, 0, 0);
    agk[tid] = -1;
    agv[tid] = 0;
    if (tid == 0) blockmax = 0ULL;
    __syncthreads();

    const ushort4 lv = *(const ushort4*)&d_label16[g];
    {
        const int q[4] = {lv.x, lv.y, lv.z, lv.w};
        const int lane = tid & 31;
        #pragma unroll
        for (int j = 0; j < 4; ++j) {
            const unsigned grp = __match_any_sync(0xFFFFFFFFu, q[j]);
            const int leader = __ffs(grp) - 1;
            if (lane == leader && q[j] != (int)BGLAB)
                atomicAdd(&hcnt[q[j]], __popc(grp));
        }
    }
    __syncthreads();

    const int4 cnts = *(const int4*)&hcnt[tid << 2];
    const int cv[4] = {cnts.x, cnts.y, cnts.z, cnts.w};
    unsigned long long localmax = 0ULL;
    #pragma unroll
    for (int j = 0; j < 4; ++j) {
        const int cnt = cv[j];
        if (cnt > 0) {
            const int node = recon(base, blockIdx.y << 5, blockIdx.x << 5, (tid << 2) + j);
            int r = node, pc = d_labels[node];
            while (pc != r) { r = pc; pc = d_labels[r]; }
            int xx = node;
            while (xx != r) { int nxt = d_labels[xx]; d_labels[xx] = r; xx = nxt; }

            unsigned h = ((unsigned)r * 2654435761u) >> 24;
            bool done = false;
            for (int probe = 0; probe < 256; ++probe) {
                const int slot = (h + probe) & 255;
                const int k = atomicCAS(&agk[slot], -1, r);
                if (k == -1 || k == r) { atomicAdd(&agv[slot], cnt); done = true; break; }
            }
            if (!done) {
                const int total = atomicAdd(&d_counts[r], cnt) + cnt;
                const unsigned long long key =
                    ((unsigned long long)(unsigned)total << 32)
                    | (unsigned long long)(0xFFFFFFFFu - (unsigned)r);
                if (key > localmax) localmax = key;
            }
        }
    }
    __syncthreads();

    const int fk = agk[tid];
    if (fk >= 0) {
        const int cnt = agv[tid];
        const int total = atomicAdd(&d_counts[fk], cnt) + cnt;
        const unsigned long long key =
            ((unsigned long long)(unsigned)total << 32)
            | (unsigned long long)(0xFFFFFFFFu - (unsigned)fk);
        if (key > localmax) localmax = key;
    }
    if (localmax) atomicMax(&blockmax, localmax);
    __syncthreads();

    if (tid == 0 && blockmax != 0ULL) {
        unsigned long long cur = *(volatile unsigned long long*)&d_winner[b];
        if (blockmax > cur) atomicMax(&d_winner[b], blockmax);
    }
}

// ---------------- kernel 4: masked output -----------------------------------
__global__ void k_write(const float* __restrict__ x, float* __restrict__ out) {
    const int i = blockIdx.x * blockDim.x + threadIdx.x;   // over NPIX/4
    const int p4 = i << 2;
    const int b = p4 >> 20;                                // HW = 2^20
    const int p = p4 & (HW - 1);

    const unsigned long long wk = d_winner[b];
    const int wroot = (int)(0xFFFFFFFFu - (unsigned)(wk & 0xFFFFFFFFu)); // no fg -> -1

    const ushort4 lv = ((const ushort4*)d_label16)[i];
    const int base = b * HW;
    const int rowbase = (p >> 10) & ~31;
    const int colbase = p & 0x3E0;

    const bool m0 = (lv.x != BGLAB) && (d_labels[recon(base, rowbase, colbase, lv.x)] == wroot);
    const bool m1 = (lv.y != BGLAB) && (d_labels[recon(base, rowbase, colbase, lv.y)] == wroot);
    const bool m2 = (lv.z != BGLAB) && (d_labels[recon(base, rowbase, colbase, lv.z)] == wroot);
    const bool m3 = (lv.w != BGLAB) && (d_labels[recon(base, rowbase, colbase, lv.w)] == wroot);

    const float* xb = x + (size_t)b * 2 * HW;
    const float4 v0 = *(const float4*)(xb + p);
    const float4 v1 = *(const float4*)(xb + HW + p);

    float4 o0, o1;
    o0.x = m0 ? v0.x : 0.0f;
    o0.y = m1 ? v0.y : 0.0f;
    o0.z = m2 ? v0.z : 0.0f;
    o0.w = m3 ? v0.w : 0.0f;
    o1.x = m0 ? v1.x : 0.0f;
    o1.y = m1 ? v1.y : 0.0f;
    o1.z = m2 ? v1.z : 0.0f;
    o1.w = m3 ? v1.w : 0.0f;

    float* ob = out + (size_t)b * 2 * HW;
    *(float4*)(ob + p) = o0;
    *(float4*)(ob + HW + p) = o1;
}

// ---------------- launcher --------------------------------------------------
extern "C" void kernel_launch(void* const* d_in, const int* in_sizes, int n_in,
                              void* d_out, int out_size) {
    const float* x = (const float*)d_in[0];
    float* out = (float*)d_out;

    dim3 grd(W / 32, H / 32, BATCH);

    k_init_local<<<grd, 256>>>(x);

    const int nb = BATCH * 2 * 31 * 1024;
    k_border<<<(nb + 255) / 256, 256>>>();

    k_count<<<grd, 256>>>();

    k_write<<<(NPIX / 4) / 256, 256>>>(x, out);
}

// round 17
// speedup vs baseline: 1.0844x; 1.0047x over previous
#include <cuda_runtime.h>
#include <stdint.h>

#define BATCH 16
#define H 1024
#define W 1024
#define HW (H*W)            // 1<<20
#define NPIX (BATCH*HW)
#define BGLAB 0xFFFFu
// tiles: 64 rows x 32 cols, 512 threads, 4 px/thread
#define TR 64
#define TC 32

// ---------------- scratch (static device globals; no allocs) ----------------
// d_label16[g]: tile-local id (0..2047) for fg pixels, 0xFFFF for bg.
// d_labels:     union-find parent store; ONLY tile-root entries are touched.
__device__ unsigned short d_label16[NPIX];
__device__ int d_labels[NPIX];
__device__ int d_counts[NPIX];
__device__ unsigned long long d_winner[BATCH];

// reconstruct global index of tile-local id v (0..2047) in tile
// (rowbase = 64-aligned, colbase = 32-aligned) of batch base
__device__ __forceinline__ int recon(int base, int rowbase, int colbase, int v) {
    return base + ((rowbase + (v >> 5)) << 10) + colbase + (v & 31);
}

// ---------------- shared-memory union-find (min-index roots) ----------------
__device__ __forceinline__ int findRootSH(int* L, int x) {   // with path halving
    int p = L[x];
    while (p != x) {
        int gp = L[p];
        if (gp != p) atomicMin(&L[x], gp);
        x = p; p = gp;
    }
    return x;
}
__device__ __forceinline__ int findRootS(int* L, int x) {    // read-only chase
    int p = L[x];
    while (p != x) { x = p; p = L[x]; }
    return p;
}
__device__ __forceinline__ void uniteS(int* L, int a, int b) {
    a = findRootSH(L, a);
    b = findRootSH(L, b);
    while (a != b) {
        if (a < b) { int t = a; a = b; b = t; }
        int old = atomicMin(&L[a], b);
        if (old == a) a = b;
        else a = old;
    }
}

// ---------------- global union-find with path halving -----------------------
__device__ __forceinline__ int findRootH(int x) {
    int p = d_labels[x];
    while (p != x) {
        int gp = d_labels[p];
        if (gp != p) atomicMin(&d_labels[x], gp);
        x = p; p = gp;
    }
    return x;
}
__device__ __forceinline__ void uniteG(int a, int b) {
    a = findRootH(a);
    b = findRootH(b);
    while (a != b) {
        if (a < b) { int t = a; a = b; b = t; }
        int old = atomicMin(&d_labels[a], b);
        if (old == a) a = b;
        else a = old;
    }
}

// ---------------- kernel 1: fg + run-based tile-local CC (512 thr) ----------
// 64x32 tile. Thread -> row = tid>>3 (0..63), cols 4*(tid&7)..+3.
// Row masks are 32-bit exactly as before; all union machinery unchanged.
__global__ __launch_bounds__(512, 4) void k_init_local(const float* __restrict__ x) {
    __shared__ int sl[TR * TC];          // 2048
    __shared__ unsigned smask[TR];       // 64

    const int tid = threadIdx.x;
    const int row = tid >> 3;           // 0..63
    const int col4 = (tid & 7) << 2;    // 0,4,...,28
    const int b = blockIdx.z;
    const int grow = (blockIdx.y << 6) + row;
    const int gcol = (blockIdx.x << 5) + col4;
    const int p = grow * W + gcol;
    const int g = b * HW + p;

    const float* xb = x + (size_t)b * 2 * HW;
    const float4 a0 = *(const float4*)(xb + p);
    const float4 a1 = *(const float4*)(xb + HW + p);

    unsigned nib = (a1.x > a0.x ? 1u : 0u) | (a1.y > a0.y ? 2u : 0u)
                 | (a1.z > a0.z ? 4u : 0u) | (a1.w > a0.w ? 8u : 0u);

    // OR-butterfly within 8-lane row groups -> full 32-bit row mask
    unsigned m = nib << (col4 & 31);
    m |= __shfl_xor_sync(0xFFFFFFFFu, m, 1);
    m |= __shfl_xor_sync(0xFFFFFFFFu, m, 2);
    m |= __shfl_xor_sync(0xFFFFFFFFu, m, 4);
    if ((tid & 7) == 0) smask[row] = m;

    // run leaders for the 4 pixels
    const unsigned runstarts = m & ~(m << 1);
    const int r32 = row << 5;
    int n0 = r32 + col4, n1 = n0 + 1, n2 = n0 + 2, n3 = n0 + 3;
    if (nib & 1u) n0 = r32 + (31 - __clz(runstarts & ((2u << (col4    )) - 1u)));
    if (nib & 2u) n1 = r32 + (31 - __clz(runstarts & ((2u << (col4 + 1)) - 1u)));
    if (nib & 4u) n2 = r32 + (31 - __clz(runstarts & ((2u << (col4 + 2)) - 1u)));
    if (nib & 8u) n3 = r32 + (31 - __clz(runstarts & ((2u << (col4 + 3)) - 1u)));
    *(int4*)&sl[r32 + col4] = make_int4(n0, n1, n2, n3);
    __syncthreads();

    const int nodes[4] = {n0, n1, n2, n3};
    if (row > 0 && nib) {
        const unsigned up = smask[row - 1];
        #pragma unroll
        for (int j = 0; j < 4; ++j) {
            if (!((nib >> j) & 1u)) continue;
            const int c = col4 + j;
            const int t = r32 + c;
            const bool Wf  = (c > 0)  && ((m >> (c - 1)) & 1u);
            const bool Ef  = (c < 31) && ((m >> (c + 1)) & 1u);
            const bool Nf  = (up >> c) & 1u;
            const bool NWf = (c > 0)  && ((up >> (c - 1)) & 1u);
            const bool NEf = (c < 31) && ((up >> (c + 1)) & 1u);
            if (Nf) {
                if (!(Wf && NWf)) uniteS(sl, nodes[j], t - 32);
            } else {
                if (NWf && !Wf) uniteS(sl, nodes[j], t - 33);
                if (NEf && !Ef) uniteS(sl, nodes[j], t - 31);
            }
        }
    }
    __syncthreads();

    // leader-only resolution + compression; root leaders do the sparse init
    #pragma unroll
    for (int j = 0; j < 4; ++j) {
        if ((nib >> j) & 1u) {
            const int t = r32 + col4 + j;
            if (nodes[j] == t) {                     // run leader
                const int r = findRootS(sl, t);
                sl[t] = r;                           // compress (true root)
                if (r == t) { d_labels[g + j] = g + j; d_counts[g + j] = 0; }
            }
        }
    }
    __syncthreads();

    // per-pixel final label: one shared read of the leader entry
    unsigned short v[4];
    #pragma unroll
    for (int j = 0; j < 4; ++j)
        v[j] = ((nib >> j) & 1u) ? (unsigned short)sl[nodes[j]]
                                 : (unsigned short)BGLAB;
    *(ushort4*)&d_label16[g] = make_ushort4(v[0], v[1], v[2], v[3]);
}

// ---------------- kernel 2: run-filtered cross-tile border merges -----------
// Horizontal boundaries now only at rows 64,128,...,960 (15/batch, was 31);
// vertical boundaries unchanged (31/batch). perB = (15+31)*1024.
__global__ void k_border() {
    const int perB = 46 * 1024;
    const int idx = blockIdx.x * blockDim.x + threadIdx.x;
    if (idx < BATCH) d_winner[idx] = 0ULL;     // reset winners (pre-k3)
    if (idx >= BATCH * perB) return;
    const int b = idx / perB;
    int j = idx - b * perB;
    const int base = b * HW;

    if (j < 15 * 1024) {
        // horizontal boundary rows 64,...,960; lane = column & 31
        const int r = 64 * (1 + (j >> 10));
        const int c = j & 1023;
        const int lane = c & 31;
        const int p = base + r * W + c;

        const int v  = d_label16[p];
        const int vn = d_label16[p - W];
        int nwv = __shfl_up_sync(0xFFFFFFFFu, vn, 1);
        int nev = __shfl_down_sync(0xFFFFFFFFu, vn, 1);
        if (lane == 0)  nwv = (c > 0)    ? (int)d_label16[p - W - 1] : (int)BGLAB;
        if (lane == 31) nev = (c < 1023) ? (int)d_label16[p - W + 1] : (int)BGLAB;
        const unsigned rowm = __ballot_sync(0xFFFFFFFFu, v != (int)BGLAB);
        const unsigned upm  = __ballot_sync(0xFFFFFFFFu, vn != (int)BGLAB);
        if (v == (int)BGLAB) return;

        const bool Wf  = lane > 0  && ((rowm >> (lane - 1)) & 1u);
        const bool Ef  = lane < 31 && ((rowm >> (lane + 1)) & 1u);
        const bool Nf  = (upm >> lane) & 1u;
        const bool NWf = nwv != (int)BGLAB;
        const bool NEf = nev != (int)BGLAB;

        const int lp = recon(base, r, c & ~31, v);          // rowbase = r (64-aligned)
        if (Nf) {
            if (!(Wf && NWf)) uniteG(lp, recon(base, r - 64, c & ~31, vn));
        } else {
            if (NWf && !Wf) uniteG(lp, recon(base, r - 64, (c - 1) & ~31, nwv));
            if (NEf && !Ef) uniteG(lp, recon(base, r - 64, (c + 1) & ~31, nev));
        }
    } else {
        // vertical boundary cols 32,...,992; lane = row & 31
        j -= 15 * 1024;
        const int c = 32 * (1 + (j >> 10));
        const int r = j & 1023;
        const int lane = r & 31;
        const int p = base + r * W + c;

        const int v  = d_label16[p];
        const int wv = d_label16[p - 1];
        int nwv = __shfl_up_sync(0xFFFFFFFFu, wv, 1);
        int swv = __shfl_down_sync(0xFFFFFFFFu, wv, 1);
        if (lane == 0)  nwv = (r > 0)    ? (int)d_label16[p - W - 1] : (int)BGLAB;
        if (lane == 31) swv = (r < 1023) ? (int)d_label16[p + W - 1] : (int)BGLAB;
        const unsigned colm = __ballot_sync(0xFFFFFFFFu, v != (int)BGLAB);
        __syncwarp();
        if (v == (int)BGLAB) return;

        const bool Nf  = lane > 0  && ((colm >> (lane - 1)) & 1u);
        const bool Sf  = lane < 31 && ((colm >> (lane + 1)) & 1u);
        const bool Wf  = wv  != (int)BGLAB;
        const bool NWf = nwv != (int)BGLAB;
        const bool SWf = swv != (int)BGLAB;

        const int lp = recon(base, r & ~63, c, v);
        if (Wf) {
            if (!(Nf && NWf)) uniteG(lp, recon(base, r & ~63, c - 32, wv));
        } else {
            if (NWf && !Nf) uniteG(lp, recon(base, (r - 1) & ~63, c - 32, nwv));
            if (SWf && !Sf) uniteG(lp, recon(base, (r + 1) & ~63, c - 32, swv));
        }
    }
}

// ---------------- kernel 3: count + compress + block-aggregated totals ------
// 64x32 tile, 512 threads, 4 px/thread. Direct-index 2048-slot histogram;
// tile roots chase to final roots (full compression; forest static), then
// (final_root,cnt) aggregated in a 512-slot shared hash: one global atomicAdd
// per distinct final root per block. Winner key: adds partition the true
// total, every partial <= total, chronologically-last add returns the exact
// total => max key = (max count, min root); jnp.argmax tie-break preserved.
__global__ __launch_bounds__(512, 4) void k_count() {
    __shared__ int hcnt[TR * TC];        // 2048
    __shared__ int agk[512];
    __shared__ int agv[512];
    __shared__ unsigned long long blockmax;

    const int tid = threadIdx.x;
    const int row = tid >> 3;            // 0..63
    const int col4 = (tid & 7) << 2;
    const int b = blockIdx.z;
    const int base = b * HW;
    const int g = base + (((blockIdx.y << 6) + row) << 10) + (blockIdx.x << 5) + col4;

    *(int4*)&hcnt[tid << 2] = make_int4(0, 0, 0, 0);
    agk[tid] = -1;
    agv[tid] = 0;
    if (tid == 0) blockmax = 0ULL;
    __syncthreads();

    const ushort4 lv = *(const ushort4*)&d_label16[g];
    if (lv.x != BGLAB) atomicAdd(&hcnt[lv.x], 1);
    if (lv.y != BGLAB) atomicAdd(&hcnt[lv.y], 1);
    if (lv.z != BGLAB) atomicAdd(&hcnt[lv.z], 1);
    if (lv.w != BGLAB) atomicAdd(&hcnt[lv.w], 1);
    __syncthreads();

    const int4 cnts = *(const int4*)&hcnt[tid << 2];
    const int cv[4] = {cnts.x, cnts.y, cnts.z, cnts.w};
    unsigned long long localmax = 0ULL;
    #pragma unroll
    for (int j = 0; j < 4; ++j) {
        const int cnt = cv[j];
        if (cnt > 0) {
            const int node = recon(base, blockIdx.y << 6, blockIdx.x << 5, (tid << 2) + j);
            int r = node, pc = d_labels[node];
            while (pc != r) { r = pc; pc = d_labels[r]; }
            int xx = node;
            while (xx != r) { int nxt = d_labels[xx]; d_labels[xx] = r; xx = nxt; }

            unsigned h = ((unsigned)r * 2654435761u) >> 23;   // 9-bit
            bool done = false;
            for (int probe = 0; probe < 512; ++probe) {
                const int slot = (h + probe) & 511;
                const int k = atomicCAS(&agk[slot], -1, r);
                if (k == -1 || k == r) { atomicAdd(&agv[slot], cnt); done = true; break; }
            }
            if (!done) {
                const int total = atomicAdd(&d_counts[r], cnt) + cnt;
                const unsigned long long key =
                    ((unsigned long long)(unsigned)total << 32)
                    | (unsigned long long)(0xFFFFFFFFu - (unsigned)r);
                if (key > localmax) localmax = key;
            }
        }
    }
    __syncthreads();

    const int fk = agk[tid];
    if (fk >= 0) {
        const int cnt = agv[tid];
        const int total = atomicAdd(&d_counts[fk], cnt) + cnt;
        const unsigned long long key =
            ((unsigned long long)(unsigned)total << 32)
            | (unsigned long long)(0xFFFFFFFFu - (unsigned)fk);
        if (key > localmax) localmax = key;
    }
    if (localmax) atomicMax(&blockmax, localmax);
    __syncthreads();

    if (tid == 0 && blockmax != 0ULL) {
        unsigned long long cur = *(volatile unsigned long long*)&d_winner[b];
        if (blockmax > cur) atomicMax(&d_winner[b], blockmax);
    }
}

// ---------------- kernel 4: masked output -----------------------------------
__global__ void k_write(const float* __restrict__ x, float* __restrict__ out) {
    const int i = blockIdx.x * blockDim.x + threadIdx.x;   // over NPIX/4
    const int p4 = i << 2;
    const int b = p4 >> 20;                                // HW = 2^20
    const int p = p4 & (HW - 1);

    const unsigned long long wk = d_winner[b];
    const int wroot = (int)(0xFFFFFFFFu - (unsigned)(wk & 0xFFFFFFFFu)); // no fg -> -1

    const ushort4 lv = ((const ushort4*)d_label16)[i];
    const int base = b * HW;
    const int rowbase = (p >> 10) & ~63;
    const int colbase = p & 0x3E0;

    const bool m0 = (lv.x != BGLAB) && (d_labels[recon(base, rowbase, colbase, lv.x)] == wroot);
    const bool m1 = (lv.y != BGLAB) && (d_labels[recon(base, rowbase, colbase, lv.y)] == wroot);
    const bool m2 = (lv.z != BGLAB) && (d_labels[recon(base, rowbase, colbase, lv.z)] == wroot);
    const bool m3 = (lv.w != BGLAB) && (d_labels[recon(base, rowbase, colbase, lv.w)] == wroot);

    const float* xb = x + (size_t)b * 2 * HW;
    const float4 v0 = *(const float4*)(xb + p);
    const float4 v1 = *(const float4*)(xb + HW + p);

    float4 o0, o1;
    o0.x = m0 ? v0.x : 0.0f;
    o0.y = m1 ? v0.y : 0.0f;
    o0.z = m2 ? v0.z : 0.0f;
    o0.w = m3 ? v0.w : 0.0f;
    o1.x = m0 ? v1.x : 0.0f;
    o1.y = m1 ? v1.y : 0.0f;
    o1.z = m2 ? v1.z : 0.0f;
    o1.w = m3 ? v1.w : 0.0f;

    float* ob = out + (size_t)b * 2 * HW;
    *(float4*)(ob + p) = o0;
    *(float4*)(ob + HW + p) = o1;
}

// ---------------- launcher --------------------------------------------------
extern "C" void kernel_launch(void* const* d_in, const int* in_sizes, int n_in,
                              void* d_out, int out_size) {
    const float* x = (const float*)d_in[0];
    float* out = (float*)d_out;

    dim3 grd(W / TC, H / TR, BATCH);    // (32, 16, 16) = 8192 blocks

    k_init_local<<<grd, 512>>>(x);

    const int nb = BATCH * 46 * 1024;
    k_border<<<(nb + 255) / 256, 256>>>();

    k_count<<<grd, 512>>>();

    k_write<<<(NPIX / 4) / 256, 256>>>(x, out);
}